// round 13
// baseline (speedup 1.0000x reference)
#include <cuda_runtime.h>
#include <cstdint>

// ---------------------------------------------------------------------------
// SCAConv decomposition (same math as R2-R11):
// out[b,o,l] = bias[o] + sum_i xu*kernel[o,i] + sum_i xu*b2[(l&31)*144+i]
//            + sum_j H[o*128+(l>>5), j] * G[b,l,j]
// G[b,l,j] = sum_i xu[b,i,l] * W2[((l&31)*144+i)*32 + j]
//
// R12: R6 per-thread shape (8b x 4c f32x2, unroll 4) kept EXACTLY, but block
// = (lh, lm-half of 16), grid 256 x 256 threads, launch_bounds(256,2) ->
// 2 CTAs/SM (occ 50%) with zero W2 duplication (halves read disjoint rows)
// and zero register-budget loss (2*256*128 = full 64k RF).
// ---------------------------------------------------------------------------

#define XS_CSTR  19                    // cols per (c,kr) row-group (18 used + 1 pad)
#define XS_OFF   0
#define XS_SIZE  (48*XS_CSTR*8)        // 7296 floats, batch innermost
#define HS_OFF   (XS_OFF + XS_SIZE)
#define HS_SIZE  (32*32)
#define BIAS_OFF (HS_OFF + HS_SIZE)
#define BIAS_SIZE 32
#define CS_OFF   (BIAS_OFF + BIAS_SIZE)
#define CS_LSTR  68                    // per-lm: 32 G + 32 conv + 2 t-halves + 2 pad
#define CS_BSTR  (16*CS_LSTR)          // 16 lm per block
#define CS_SIZE  (8*CS_BSTR)           // 8704
#define SMEM_FLOATS (CS_OFF + CS_SIZE) // 17056 floats = 68.2 KB per CTA

__device__ float g_kT[144*32];         // kernel transposed: kT[i][o]

__global__ void prep_kernel(const float* __restrict__ kern) {
    int idx = blockIdx.x * 256 + threadIdx.x;
    if (idx < 4608) {
        int i = idx >> 5, o = idx & 31;
        g_kT[idx] = kern[o*144 + i];
    }
}

typedef unsigned long long ull;

#define PACK2(d, s)      asm("mov.b64 %0, {%1, %1};" : "=l"(d) : "f"(s))
#define UNPACK2(lo, hi, v) asm("mov.b64 {%0, %1}, %2;" : "=f"(lo), "=f"(hi) : "l"(v))
#define FMA2(acc, a, b)  asm("fma.rn.f32x2 %0, %1, %2, %0;" : "+l"(acc) : "l"(a), "l"(b))

__global__ __launch_bounds__(256, 2)
void sca_kernel(const float* __restrict__ x, const float* __restrict__ bias,
                const float* __restrict__ cpar,
                const float* __restrict__ W1, const float* __restrict__ b1,
                const float* __restrict__ W2, const float* __restrict__ b2,
                float* __restrict__ out)
{
    extern __shared__ float sm[];
    float* xs = sm + XS_OFF;
    float* Hs = sm + HS_OFF;
    float* bs = sm + BIAS_OFF;
    float* Cs = sm + CS_OFF;

    const int tid  = threadIdx.x;
    const int lh   = blockIdx.x >> 1;    // 0..127
    const int half = blockIdx.x & 1;     // lm-half: lm = half*16 + lmi
    const int R    = lh >> 1;
    const int C0h  = (lh & 1) * 32 + half * 16;  // first output col of this block

    // ---------- setup: x patch for 18 cols, batch-innermost ----------
    // xs[((c*3+kr)*19 + cc)*8 + b] = x[b][c][R-1+kr][C0h-1+cc]
    for (int idx = tid; idx < 8*16*3*18; idx += 256) {
        int cc = idx % 18;
        int t2 = idx / 18;
        int kr = t2 % 3;  t2 /= 3;
        int c  = t2 % 16;
        int b  = t2 / 16;
        int r   = R - 1 + kr;
        int col = C0h - 1 + cc;
        float v = 0.f;
        if (r >= 0 && r < 64 && col >= 0 && col < 64)
            v = x[((b*16 + c)*64 + r)*64 + col];
        xs[((c*3 + kr)*XS_CSTR + cc)*8 + b] = v;
    }

    // ---------- H rows: H[o*128+lh][j], thread (o, j-quad) ----------
    {
        int o  = tid >> 3;             // 0..31
        int jq = tid & 7;              // 4 j per thread
        int p  = o*128 + lh;
        float inp[12];
        inp[0] = (float)(p >> 6) * (1.f/64.f);
        inp[1] = 1.f - inp[0];
        inp[2] = (float)(p & 63) * (1.f/64.f);
        inp[3] = 1.f - inp[2];
        #pragma unroll
        for (int k = 0; k < 8; k++) inp[4+k] = cpar[k];
        #pragma unroll
        for (int jj = 0; jj < 4; jj++) {
            int j = jq*4 + jj;
            float s = b1[j];
            #pragma unroll
            for (int k = 0; k < 12; k++) s += W1[j*12 + k] * inp[k];
            Hs[o*32 + j] = fmaxf(s, 0.f);
        }
    }
    if (tid < 32) bs[tid] = bias[tid];
    __syncthreads();

    // ---------- main loop: 8 batches x 4 cols per thread (R6 body) ----------
    // tid = part*128 + lmi*8 + cg ; part 0: G cols j = cg*4..+3 (W2, L2-hot)
    //                               part 1: conv cols o = cg*4..+3 (g_kT, L1)
    {
        const int part = tid >> 7;
        const int t    = tid & 127;
        const int lmi  = t >> 3;       // 0..15
        const int cg   = t & 7;
        const int lm   = half*16 + lmi;

        const float* wp = part ? (g_kT + cg*4) : (W2 + lm*4608 + cg*4);
        const float* xp = xs + lmi*8;

        ull acc[4][4];   // [col n][batch pair bp]
        #pragma unroll
        for (int n = 0; n < 4; n++)
            #pragma unroll
            for (int bp = 0; bp < 4; bp++) acc[n][bp] = 0ull;

        #pragma unroll 4
        for (int c = 0; c < 16; ++c) {
            const float* xc = xp + c*(3*XS_CSTR*8);
            const float* wc = wp + c*(9*32);
            #pragma unroll
            for (int kr = 0; kr < 3; ++kr) {
                #pragma unroll
                for (int kc = 0; kc < 3; ++kc) {
                    const float* xr = xc + (kr*XS_CSTR + kc)*8;
                    ulonglong2 xa = *(const ulonglong2*)(xr);      // b0..b3
                    ulonglong2 xb = *(const ulonglong2*)(xr + 4);  // b4..b7
                    float4 w = *(const float4*)(wc + (kr*3 + kc)*32);
                    ull wpk[4];
                    PACK2(wpk[0], w.x); PACK2(wpk[1], w.y);
                    PACK2(wpk[2], w.z); PACK2(wpk[3], w.w);
                    #pragma unroll
                    for (int n = 0; n < 4; n++) {
                        FMA2(acc[n][0], xa.x, wpk[n]);
                        FMA2(acc[n][1], xa.y, wpk[n]);
                        FMA2(acc[n][2], xb.x, wpk[n]);
                        FMA2(acc[n][3], xb.y, wpk[n]);
                    }
                }
            }
        }

        // unpack -> per-batch float4 stores
        float f[8][4];
        #pragma unroll
        for (int n = 0; n < 4; n++)
            #pragma unroll
            for (int bp = 0; bp < 4; bp++)
                UNPACK2(f[2*bp][n], f[2*bp+1][n], acc[n][bp]);
        float* cb = Cs + lmi*CS_LSTR + part*32 + cg*4;
        #pragma unroll
        for (int b = 0; b < 8; b++)
            *(float4*)(cb + b*CS_BSTR) = make_float4(f[b][0], f[b][1], f[b][2], f[b][3]);
    }

    // ---------- t-term, distributed: 128 (b,lmi) outputs x 2 i-halves ----------
    {
        const int ih   = tid >> 7;         // 0/1: c in [ih*8, ih*8+8)
        const int idx  = tid & 127;
        const int b    = idx & 7;
        const int lmi2 = idx >> 3;         // 0..15
        const float* bp2 = b2 + (half*16 + lmi2)*144;
        float tacc = 0.f;
        #pragma unroll 2
        for (int c = ih*8; c < ih*8 + 8; ++c) {
            #pragma unroll
            for (int kr = 0; kr < 3; ++kr) {
                #pragma unroll
                for (int kc = 0; kc < 3; ++kc) {
                    float xv = xs[((c*3 + kr)*XS_CSTR + lmi2 + kc)*8 + b];
                    tacc += xv * bp2[c*9 + kr*3 + kc];
                }
            }
        }
        Cs[b*CS_BSTR + lmi2*CS_LSTR + 64 + ih] = tacc;
    }
    __syncthreads();

    // ---------- epilogue: out = bias + t + conv + H·G ----------
    {
        int b    = tid >> 5;           // 0..7
        int oh   = (tid >> 4) & 1;     // o-half: o = oh*16 .. +15
        int lmi3 = tid & 15;
        const float* cb = Cs + b*CS_BSTR + lmi3*CS_LSTR;

        float g[32];
        #pragma unroll
        for (int q = 0; q < 8; q++) {
            float4 v = *(const float4*)(cb + q*4);
            g[q*4+0] = v.x; g[q*4+1] = v.y; g[q*4+2] = v.z; g[q*4+3] = v.w;
        }
        float cw[16];
        #pragma unroll
        for (int q = 0; q < 4; q++) {
            float4 v = *(const float4*)(cb + 32 + oh*16 + q*4);
            cw[q*4+0] = v.x; cw[q*4+1] = v.y; cw[q*4+2] = v.z; cw[q*4+3] = v.w;
        }
        float tv = cb[64] + cb[65];

        float* ob = out + b*(32*4096) + (oh*16)*4096 + lh*32 + half*16 + lmi3;
        #pragma unroll
        for (int oo = 0; oo < 16; oo++) {
            int o = oh*16 + oo;
            float s = bs[o] + tv + cw[oo];
            const float4* h4 = (const float4*)(Hs + o*32);
            #pragma unroll
            for (int q = 0; q < 8; q++) {
                float4 h = h4[q];
                s += h.x*g[q*4] + h.y*g[q*4+1] + h.z*g[q*4+2] + h.w*g[q*4+3];
            }
            ob[oo*4096] = s;
        }
    }
}

extern "C" void kernel_launch(void* const* d_in, const int* in_sizes, int n_in,
                              void* d_out, int out_size)
{
    const float* x    = (const float*)d_in[0];   // (8,16,64,64)
    const float* kern = (const float*)d_in[1];   // (32,144)
    const float* bias = (const float*)d_in[2];   // (32,)
    const float* cpar = (const float*)d_in[3];   // (1,8)
    const float* W1   = (const float*)d_in[4];   // (32,12)
    const float* b1   = (const float*)d_in[5];   // (32,)
    const float* W2   = (const float*)d_in[6];   // (4608,32)
    const float* b2   = (const float*)d_in[7];   // (4608,)
    float* out = (float*)d_out;                  // (8,32,64,64)

    prep_kernel<<<18, 256>>>(kern);
    cudaFuncSetAttribute(sca_kernel, cudaFuncAttributeMaxDynamicSharedMemorySize,
                         SMEM_FLOATS * 4);
    sca_kernel<<<256, 256, SMEM_FLOATS * 4>>>(x, bias, cpar, W1, b1, W2, b2, out);
}